// round 8
// baseline (speedup 1.0000x reference)
#include <cuda_runtime.h>
#include <math.h>

#define B_SZ   64
#define IN_SZ  1024
#define OUT_SZ 512
#define T_SZ   512
#define TAU_F  16.0f
#define V_TH   1.0f
#define WIN    8
#define NWE    32          // entry windows (spikes < 256 -> k <= 256)
#define NW     64          // total windows
#define ESTRIDE 1056
#define CHP    8           // partial prefetch depth
#define CHW    4           // window prefetch depth (lower regs)
#define SENT_MAX 256
#define DFACT  0.60653065971263342f   // exp(-WIN/TAU) = exp(-0.5)

// Scratch (no dynamic allocation allowed)
__device__ float4 g_entries[B_SZ * ESTRIDE];        // {k, idx, u, p} sorted per batch
__device__ float  g_wT[IN_SZ * OUT_SZ];             // transposed weights [IN][OUT]
__device__ int    g_wstart[B_SZ * (NWE + 1)];       // per-batch window entry offsets
__device__ float2 g_P[B_SZ * NWE * OUT_SZ];         // per-window partials {PA, PB}
__device__ float2 g_S[B_SZ * NWE * OUT_SZ];         // per-window start state {A, B}

// ---------------------------------------------------------------------------
// Prep: blocks [0,64) bucket-sort spikes per batch (warp-shuffle scan) +
// window offsets + output init; blocks [64,192) float4 tiled transpose.
// ---------------------------------------------------------------------------
__global__ void __launch_bounds__(1024) prep_kernel(const float* __restrict__ in_spike,
                                                    const float* __restrict__ w,
                                                    float* __restrict__ out) {
    __shared__ int   hist[512];
    __shared__ int   scanv[512];
    __shared__ int   offs[512];
    __shared__ int   wsum[16];
    __shared__ float tile[64][65];

    const int bid = blockIdx.x;
    const int i   = threadIdx.x;

    if (bid < B_SZ) {
        const int b = bid;
        if (i < 512) { hist[i] = 0; out[b * OUT_SZ + i] = 512.0f; }  // init for atomicMin
        __syncthreads();

        const float s = in_spike[b * IN_SZ + i];
        int k = (int)floorf(s) + 1;
        k = max(1, min(k, NWE * WIN));           // k in [1, 256]
        atomicAdd(&hist[k], 1);
        __syncthreads();

        int h0 = 0, incl = 0;
        if (i < 512) {
            h0 = hist[i]; incl = h0;
            #pragma unroll
            for (int d = 1; d < 32; d <<= 1) {
                int n = __shfl_up_sync(0xffffffffu, incl, d);
                if ((i & 31) >= d) incl += n;
            }
            if ((i & 31) == 31) wsum[i >> 5] = incl;
        }
        __syncthreads();
        if (i < 16) {
            int s2 = wsum[i];
            #pragma unroll
            for (int d = 1; d < 16; d <<= 1) {
                int n = __shfl_up_sync(0x0000ffffu, s2, d);
                if (i >= d) s2 += n;
            }
            wsum[i] = s2;
        }
        __syncthreads();
        if (i < 512) {
            const int wrp = i >> 5;
            if (wrp > 0) incl += wsum[wrp - 1];
            scanv[i] = incl;          // inclusive
            offs[i]  = incl - h0;     // exclusive
        }
        __syncthreads();
        if (i <= NWE) g_wstart[b * (NWE + 1) + i] = (i == 0) ? 0 : scanv[i * WIN];

        const int pos = atomicAdd(&offs[k], 1);
        const int t0k = (k - 1) & ~(WIN - 1);
        const float rel = s - (float)t0k;              // [0, WIN)
        const float u = expf(rel * (1.0f / TAU_F));
        const float p = rel * u;
        g_entries[b * ESTRIDE + pos] = make_float4((float)k, (float)i, u, p);
    } else {
        // transpose 64x64 tile: w[OUT][IN] -> g_wT[IN][OUT]
        const int tb = bid - B_SZ;                 // 0..127
        const int i0 = (tb & 15) * 64;             // IN tile (16 tiles)
        const int o0 = (tb >> 4) * 64;             // OUT tile (8 tiles)
        const int tx = i & 15, ty = i >> 4;        // 16 x 64
        const float4 v = *(const float4*)&w[(o0 + ty) * IN_SZ + i0 + 4 * tx];
        tile[4 * tx + 0][ty] = v.x;
        tile[4 * tx + 1][ty] = v.y;
        tile[4 * tx + 2][ty] = v.z;
        tile[4 * tx + 3][ty] = v.w;
        __syncthreads();
        float4 r;
        r.x = tile[ty][4 * tx + 0];
        r.y = tile[ty][4 * tx + 1];
        r.z = tile[ty][4 * tx + 2];
        r.w = tile[ty][4 * tx + 3];
        *(float4*)&g_wT[(i0 + ty) * OUT_SZ + o0 + 4 * tx] = r;
    }
}

// ---------------------------------------------------------------------------
// Phase 2: per-window partial sums, 4 outputs/thread. Grid (NWE, B).
// ---------------------------------------------------------------------------
__global__ void __launch_bounds__(128) partial_kernel() {
    __shared__ float4 sent[SENT_MAX];
    const int W = blockIdx.x, b = blockIdx.y;
    const int tid = threadIdx.x;

    const int start = g_wstart[b * (NWE + 1) + W];
    const int count = g_wstart[b * (NWE + 1) + W + 1] - start;

    const float4* __restrict__ ge = g_entries + b * ESTRIDE + start;
    const float4* __restrict__ wp = (const float4*)g_wT + tid;
    float PA0 = 0.f, PB0 = 0.f, PA1 = 0.f, PB1 = 0.f;
    float PA2 = 0.f, PB2 = 0.f, PA3 = 0.f, PB3 = 0.f;

    for (int base = 0; base < count; base += SENT_MAX) {
        const int tcount = min(count - base, SENT_MAX);
        const int padded = (tcount + CHP - 1) & ~(CHP - 1);
        for (int j = tid; j < padded; j += 128)
            sent[j] = (j < tcount) ? ge[base + j] : make_float4(1e9f, 0.f, 0.f, 0.f);
        __syncthreads();

        float4 wc[CHP];
        #pragma unroll
        for (int q = 0; q < CHP; q++) wc[q] = wp[((int)sent[q].y) << 7];
        const int nch = padded / CHP;
        for (int c = 0; c < nch; c++) {
            float4 wn[CHP];
            if (c + 1 < nch) {
                #pragma unroll
                for (int q = 0; q < CHP; q++)
                    wn[q] = wp[((int)sent[(c + 1) * CHP + q].y) << 7];
            }
            #pragma unroll
            for (int q = 0; q < CHP; q++) {
                const float4 e = sent[c * CHP + q];       // pads have u=p=0
                PA0 = fmaf(wc[q].x, e.z, PA0); PB0 = fmaf(wc[q].x, e.w, PB0);
                PA1 = fmaf(wc[q].y, e.z, PA1); PB1 = fmaf(wc[q].y, e.w, PB1);
                PA2 = fmaf(wc[q].z, e.z, PA2); PB2 = fmaf(wc[q].z, e.w, PB2);
                PA3 = fmaf(wc[q].w, e.z, PA3); PB3 = fmaf(wc[q].w, e.w, PB3);
            }
            #pragma unroll
            for (int q = 0; q < CHP; q++) wc[q] = wn[q];
        }
        __syncthreads();
    }
    float2* Pp = &g_P[(b * NWE + W) * OUT_SZ + 4 * tid];
    *(float4*)(Pp)     = make_float4(PA0, PB0, PA1, PB1);
    *(float4*)(Pp + 2) = make_float4(PA2, PB2, PA3, PB3);
}

// ---------------------------------------------------------------------------
// Phase 3a: window-prefix scan A' = D(A+PA), B' = D(B+PB) - WIN*A'.
// Writes start state for windows 0..NWE-1; evaluates entry-free tail
// windows NWE..NW-1 via threshold table; first crossing -> atomicMin.
// ---------------------------------------------------------------------------
__global__ void __launch_bounds__(128) scan_kernel(float* __restrict__ out) {
    __shared__ float sthresh[WIN + 1];
    const int b = blockIdx.y;
    const int o = blockIdx.x * 128 + threadIdx.x;
    if (threadIdx.x >= 1 && threadIdx.x <= WIN) {
        const float dec = expf(1.0f - (float)threadIdx.x * (1.0f / TAU_F)) * (1.0f / TAU_F);
        sthresh[threadIdx.x] = V_TH / dec;
    }
    __syncthreads();

    float2 P[NWE];
    #pragma unroll
    for (int w = 0; w < NWE; w++) P[w] = g_P[(b * NWE + w) * OUT_SZ + o];

    float As = 0.f, Bs = 0.f;
    #pragma unroll
    for (int W = 0; W < NWE; W++) {
        if (W > 0) {
            As = DFACT * (As + P[W - 1].x);
            Bs = DFACT * (Bs + P[W - 1].y) - (float)WIN * As;
        }
        g_S[(b * NWE + W) * OUT_SZ + o] = make_float2(As, Bs);
    }
    int found = 0, result = 0;
    for (int W = NWE; W < NW && !found; W++) {
        const float pa = (W == NWE) ? P[NWE - 1].x : 0.f;
        const float pb = (W == NWE) ? P[NWE - 1].y : 0.f;
        As = DFACT * (As + pa);
        Bs = DFACT * (Bs + pb) - (float)WIN * As;
        int c = 1000;
        #pragma unroll
        for (int dt = 1; dt <= WIN; dt++) {
            if (fmaf((float)dt, As, -Bs) >= sthresh[dt]) c = min(c, dt);
        }
        if (c <= WIN) { found = 1; result = W * WIN + c; }
    }
    if (found)
        atomicMin((int*)out + b * OUT_SZ + o, __float_as_int((float)result));
}

// ---------------------------------------------------------------------------
// Phase 3b: per-window evaluation for entry windows, 4 outputs/thread.
// Grid (NWE, B), 128 threads cover all 512 outputs.
// ---------------------------------------------------------------------------
__global__ void __launch_bounds__(128) window_kernel(float* __restrict__ out) {
    __shared__ float4 sent[SENT_MAX];
    __shared__ float  sthresh[WIN + 1];
    const int W = blockIdx.x, b = blockIdx.y;
    const int tid = threadIdx.x;
    const int o = 4 * tid;

    if (tid >= 1 && tid <= WIN) {
        const float dec = expf(1.0f - (float)tid * (1.0f / TAU_F)) * (1.0f / TAU_F);
        sthresh[tid] = V_TH / dec;
    }

    const int start = g_wstart[b * (NWE + 1) + W];
    const int count = g_wstart[b * (NWE + 1) + W + 1] - start;
    const float kbase = (float)(W * WIN);

    const float2* Sp = &g_S[(b * NWE + W) * OUT_SZ + o];
    const float4 s01 = *(const float4*)(Sp);
    const float4 s23 = *(const float4*)(Sp + 2);
    float A0 = s01.x, B0 = s01.y, A1 = s01.z, B1 = s01.w;
    float A2 = s23.x, B2 = s23.y, A3 = s23.z, B3 = s23.w;

    const float4* __restrict__ ge = g_entries + b * ESTRIDE + start;
    const float4* __restrict__ wp = (const float4*)g_wT + tid;

    int t_dt = 1, cand0 = 1000, cand1 = 1000, cand2 = 1000, cand3 = 1000;

    for (int base = 0; base < count; base += SENT_MAX) {
        const int tcount = min(count - base, SENT_MAX);
        const int padded = (tcount + CHW - 1) & ~(CHW - 1);
        for (int j = tid; j < padded; j += 128) {
            float4 e = (j < tcount) ? ge[base + j] : make_float4(1e9f, 0.f, 0.f, 0.f);
            e.x -= kbase;                       // window-relative arrival
            sent[j] = e;
        }
        __syncthreads();

        float4 wc[CHW];
        #pragma unroll
        for (int q = 0; q < CHW; q++) wc[q] = wp[((int)sent[q].y) << 7];
        const int nch = padded / CHW;
        for (int c = 0; c < nch; c++) {
            float4 wn[CHW];
            if (c + 1 < nch) {
                #pragma unroll
                for (int q = 0; q < CHW; q++)
                    wn[q] = wp[((int)sent[(c + 1) * CHW + q].y) << 7];
            }
            #pragma unroll
            for (int q = 0; q < CHW; q++) {
                const float4 e = sent[c * CHW + q];
                while ((float)t_dt < e.x && t_dt <= WIN) {   // uniform across block
                    const float tf = (float)t_dt;
                    const float th = sthresh[t_dt];
                    if (fmaf(tf, A0, -B0) >= th) cand0 = min(cand0, t_dt);
                    if (fmaf(tf, A1, -B1) >= th) cand1 = min(cand1, t_dt);
                    if (fmaf(tf, A2, -B2) >= th) cand2 = min(cand2, t_dt);
                    if (fmaf(tf, A3, -B3) >= th) cand3 = min(cand3, t_dt);
                    t_dt++;
                }
                A0 = fmaf(wc[q].x, e.z, A0); B0 = fmaf(wc[q].x, e.w, B0);
                A1 = fmaf(wc[q].y, e.z, A1); B1 = fmaf(wc[q].y, e.w, B1);
                A2 = fmaf(wc[q].z, e.z, A2); B2 = fmaf(wc[q].z, e.w, B2);
                A3 = fmaf(wc[q].w, e.z, A3); B3 = fmaf(wc[q].w, e.w, B3);
            }
            #pragma unroll
            for (int q = 0; q < CHW; q++) wc[q] = wn[q];
        }
        __syncthreads();
    }
    while (t_dt <= WIN) {                                    // tail / empty window
        const float tf = (float)t_dt;
        const float th = sthresh[t_dt];
        if (fmaf(tf, A0, -B0) >= th) cand0 = min(cand0, t_dt);
        if (fmaf(tf, A1, -B1) >= th) cand1 = min(cand1, t_dt);
        if (fmaf(tf, A2, -B2) >= th) cand2 = min(cand2, t_dt);
        if (fmaf(tf, A3, -B3) >= th) cand3 = min(cand3, t_dt);
        t_dt++;
    }
    int* ob = (int*)out + b * OUT_SZ;
    if (cand0 <= WIN) atomicMin(ob + o,     __float_as_int(kbase + (float)cand0));
    if (cand1 <= WIN) atomicMin(ob + o + 1, __float_as_int(kbase + (float)cand1));
    if (cand2 <= WIN) atomicMin(ob + o + 2, __float_as_int(kbase + (float)cand2));
    if (cand3 <= WIN) atomicMin(ob + o + 3, __float_as_int(kbase + (float)cand3));
}

// ---------------------------------------------------------------------------
extern "C" void kernel_launch(void* const* d_in, const int* in_sizes, int n_in,
                              void* d_out, int out_size) {
    const float* in_spike = (const float*)d_in[0];  // [B, IN]
    const float* weight   = (const float*)d_in[1];  // [OUT, IN]
    float* out = (float*)d_out;                     // [B, OUT]
    (void)in_sizes; (void)n_in; (void)out_size;

    prep_kernel<<<B_SZ + 128, 1024>>>(in_spike, weight, out);
    partial_kernel<<<dim3(NWE, B_SZ), 128>>>();
    scan_kernel<<<dim3(OUT_SZ / 128, B_SZ), 128>>>(out);
    window_kernel<<<dim3(NWE, B_SZ), 128>>>(out);
}